// round 2
// baseline (speedup 1.0000x reference)
#include <cuda_runtime.h>
#include <cuda_bf16.h>
#include <math.h>

#define T_TOK 16384
#define N_EXP 256
#define HID   4096

// Scratch (device globals are allowed; no allocation APIs used).
__device__ float g_logits[(size_t)T_TOK * N_EXP];
__device__ float g_small[(size_t)T_TOK * 16];

// ---------------------------------------------------------------------------
// GEMM: logits[T, 256] = x[T, 4096] @ W[256, 4096]^T   (fp32, FFMA2 packed)
// ---------------------------------------------------------------------------
#define BM 128
#define BN 64
#define BK 16
// 256 threads: tx in [0,16) covers N (16*4=64), ty in [0,16) covers M (16*8=128)

__device__ __forceinline__ unsigned long long pack2(float lo, float hi) {
    unsigned long long r;
    asm("mov.b64 %0, {%1, %2};" : "=l"(r) : "f"(lo), "f"(hi));
    return r;
}
__device__ __forceinline__ void ffma2(unsigned long long& d, unsigned long long a,
                                      unsigned long long b) {
    asm("fma.rn.f32x2 %0, %1, %2, %0;" : "+l"(d) : "l"(a), "l"(b));
}

__global__ void __launch_bounds__(256) gate_gemm(const float* __restrict__ A,
                                                 const float* __restrict__ B,
                                                 float* __restrict__ Copt) {
    float* C = Copt ? Copt : g_logits;
    __shared__ float As[BK][BM + 4];  // 132 floats/row: 528B, 16B-aligned, conflict-reduced
    __shared__ float Bs[BK][BN + 4];  // 68 floats/row: 272B, 16B-aligned

    const int tid = threadIdx.x;
    const int bm = blockIdx.x * BM;
    const int bn = blockIdx.y * BN;
    const int tx = tid & 15;        // N tile coord
    const int ty = tid >> 4;        // M tile coord
    const int lr = tid >> 2;        // loader row 0..63
    const int lc = (tid & 3) * 4;   // loader col 0,4,8,12

    const float4* aptr0 = reinterpret_cast<const float4*>(A + (size_t)(bm + lr) * HID + lc);
    const float4* aptr1 = reinterpret_cast<const float4*>(A + (size_t)(bm + lr + 64) * HID + lc);
    const float4* bptr  = reinterpret_cast<const float4*>(B + (size_t)(bn + lr) * HID + lc);

    unsigned long long acc[4][4];  // [m-pair][n], each holds 2 fp32 along M
#pragma unroll
    for (int i = 0; i < 4; ++i)
#pragma unroll
        for (int j = 0; j < 4; ++j) acc[i][j] = 0ull;  // bits of {0.0f, 0.0f}

    for (int kt = 0; kt < HID / BK; ++kt) {
        float4 av0 = aptr0[kt * (BK / 4)];
        float4 av1 = aptr1[kt * (BK / 4)];
        float4 bv  = bptr [kt * (BK / 4)];

        As[lc + 0][lr]      = av0.x; As[lc + 1][lr]      = av0.y;
        As[lc + 2][lr]      = av0.z; As[lc + 3][lr]      = av0.w;
        As[lc + 0][lr + 64] = av1.x; As[lc + 1][lr + 64] = av1.y;
        As[lc + 2][lr + 64] = av1.z; As[lc + 3][lr + 64] = av1.w;
        Bs[lc + 0][lr] = bv.x; Bs[lc + 1][lr] = bv.y;
        Bs[lc + 2][lr] = bv.z; Bs[lc + 3][lr] = bv.w;
        __syncthreads();

#pragma unroll
        for (int kk = 0; kk < BK; ++kk) {
            // a pairs come packed directly from the LDS.128: (m0,m1),(m2,m3),(m4,m5),(m6,m7)
            ulonglong2 a0 = *reinterpret_cast<const ulonglong2*>(&As[kk][ty * 8]);
            ulonglong2 a1 = *reinterpret_cast<const ulonglong2*>(&As[kk][ty * 8 + 4]);
            float4 b = *reinterpret_cast<const float4*>(&Bs[kk][tx * 4]);
            unsigned long long bb0 = pack2(b.x, b.x);
            unsigned long long bb1 = pack2(b.y, b.y);
            unsigned long long bb2 = pack2(b.z, b.z);
            unsigned long long bb3 = pack2(b.w, b.w);

            ffma2(acc[0][0], a0.x, bb0); ffma2(acc[0][1], a0.x, bb1);
            ffma2(acc[0][2], a0.x, bb2); ffma2(acc[0][3], a0.x, bb3);
            ffma2(acc[1][0], a0.y, bb0); ffma2(acc[1][1], a0.y, bb1);
            ffma2(acc[1][2], a0.y, bb2); ffma2(acc[1][3], a0.y, bb3);
            ffma2(acc[2][0], a1.x, bb0); ffma2(acc[2][1], a1.x, bb1);
            ffma2(acc[2][2], a1.x, bb2); ffma2(acc[2][3], a1.x, bb3);
            ffma2(acc[3][0], a1.y, bb0); ffma2(acc[3][1], a1.y, bb1);
            ffma2(acc[3][2], a1.y, bb2); ffma2(acc[3][3], a1.y, bb3);
        }
        __syncthreads();
    }

#pragma unroll
    for (int mp = 0; mp < 4; ++mp) {
#pragma unroll
        for (int j = 0; j < 4; ++j) {
            float2 v = *reinterpret_cast<float2*>(&acc[mp][j]);
            int m = bm + ty * 8 + mp * 2;
            int n = bn + tx * 4 + j;
            C[(size_t)m * N_EXP + n]       = v.x;
            C[(size_t)(m + 1) * N_EXP + n] = v.y;
        }
    }
}

// ---------------------------------------------------------------------------
// Routing: sigmoid -> group top-2 sums -> top-4 groups -> masked top-8
//          -> gather raw scores -> normalize * 2.5
// One warp per token; lane l owns experts [l*8, l*8+8) (one group = 4 lanes).
// ---------------------------------------------------------------------------
__global__ void __launch_bounds__(128) routing_kernel(const float* __restrict__ logits_opt,
                                                      const float* __restrict__ bias,
                                                      float* idx_opt, float* wt_opt) {
    const float* lg = logits_opt ? logits_opt : g_logits;
    float* idx_out = idx_opt ? idx_opt : g_small;
    float* wt_out  = wt_opt  ? wt_opt  : (g_small + (size_t)T_TOK * 8);

    int tok = (int)((blockIdx.x * blockDim.x + threadIdx.x) >> 5);
    int lane = threadIdx.x & 31;
    if (tok >= T_TOK) return;

    const float* row = lg + (size_t)tok * N_EXP;
    float s[8], sr[8];
#pragma unroll
    for (int i = 0; i < 8; ++i) {
        float x = row[lane * 8 + i];
        float sc = 1.0f / (1.0f + expf(-x));
        s[i]  = sc;                        // raw score (for weights)
        sr[i] = sc + bias[lane * 8 + i];   // routing score
    }

    // Per-lane top-2 of its 8 routing scores.
    float m1 = -INFINITY, m2 = -INFINITY;
#pragma unroll
    for (int i = 0; i < 8; ++i) {
        if (sr[i] > m1) { m2 = m1; m1 = sr[i]; }
        else if (sr[i] > m2) { m2 = sr[i]; }
    }
    // Merge top-2 across the 4 lanes of the group (xor 1,2 stay within lane/4 group).
#pragma unroll
    for (int off = 1; off <= 2; off <<= 1) {
        float o1 = __shfl_xor_sync(0xffffffffu, m1, off);
        float o2 = __shfl_xor_sync(0xffffffffu, m2, off);
        if (o1 > m1) { m2 = fmaxf(m1, o2); m1 = o1; }
        else         { m2 = fmaxf(m2, o1); }
    }
    float gsum = m1 + m2;  // group score (valid on all 4 lanes of the group)

    float gs[8];
#pragma unroll
    for (int g = 0; g < 8; ++g) gs[g] = __shfl_sync(0xffffffffu, gsum, g * 4);

    // Top-4 groups; ties broken toward smaller group index (jax stable top_k).
    int myg = lane >> 2;
    int rank = 0;
#pragma unroll
    for (int g = 0; g < 8; ++g)
        rank += (gs[g] > gs[myg]) || (gs[g] == gs[myg] && g < myg);
    bool group_sel = rank < 4;

    float ms[8];
#pragma unroll
    for (int i = 0; i < 8; ++i) ms[i] = group_sel ? sr[i] : -INFINITY;

    // Masked top-8, stable (equal values -> smaller expert index first).
    bool used[8] = {false, false, false, false, false, false, false, false};
    int   sel_idx[8];
    float sel_s[8];
    float wsum = 0.0f;
    for (int k = 0; k < 8; ++k) {
        float bv = -INFINITY; int bi = 0x7fffffff;
#pragma unroll
        for (int i = 0; i < 8; ++i) {
            if (!used[i] && ms[i] > bv) { bv = ms[i]; bi = lane * 8 + i; }
        }
#pragma unroll
        for (int off = 16; off >= 1; off >>= 1) {
            float ov = __shfl_xor_sync(0xffffffffu, bv, off);
            int   oi = __shfl_xor_sync(0xffffffffu, bi, off);
            if (ov > bv || (ov == bv && oi < bi)) { bv = ov; bi = oi; }
        }
        int src = bi >> 3, slot = bi & 7;
        if (lane == src) used[slot] = true;
        float sc = 0.0f;
#pragma unroll
        for (int j = 0; j < 8; ++j)
            if (j == slot) sc = s[j];
        sc = __shfl_sync(0xffffffffu, sc, src);
        sel_idx[k] = bi;
        sel_s[k]   = sc;
        wsum += sc;
    }

    float scale = 2.5f / (wsum + 1e-20f);
    if (lane == 0) {
#pragma unroll
        for (int k = 0; k < 8; ++k) {
            idx_out[(size_t)tok * 8 + k] = (float)sel_idx[k];
            wt_out [(size_t)tok * 8 + k] = sel_s[k] * scale;
        }
    }
}

// ---------------------------------------------------------------------------
extern "C" void kernel_launch(void* const* d_in, const int* in_sizes, int n_in,
                              void* d_out, int out_size) {
    const float* x    = (const float*)d_in[0];
    const float* w    = (const float*)d_in[1];
    const float* bias = (const float*)d_in[2];
    float* out = (float*)d_out;

    const long long TE  = (long long)T_TOK * N_EXP;  // 4,194,304 logits
    const long long TK2 = (long long)T_TOK * 16;     // idx + weight
    const long long TK  = (long long)T_TOK * 8;
    long long os = out_size;

    // Resolve output layout: reference returns (topk_idx, topk_weight, logits);
    // assume flat float32 concat in that order. Fall back gracefully on other sizes.
    float *idxp = nullptr, *wtp = nullptr, *lgp = nullptr;  // null -> device scratch
    if (os >= TK2 + TE) {
        idxp = out; wtp = out + TK; lgp = out + TK2;
    } else if (os == TE) {
        lgp = out;
    } else if (os == TK2) {
        idxp = out; wtp = out + TK;
    } else if (os == TK) {
        idxp = out;  // first return
    }

    dim3 grid(T_TOK / BM, N_EXP / BN);
    gate_gemm<<<grid, 256>>>(x, w, lgp);
    routing_kernel<<<T_TOK / 4, 128>>>(lgp, bias, idxp, wtp);
}